// round 14
// baseline (speedup 1.0000x reference)
#include <cuda_runtime.h>
#include <cuda_bf16.h>
#include <cstdint>
#include <math.h>

// ---------------- problem constants ----------------
#define Bn 4
#define Tn 512
#define Vn 576
#define Ln 256
#define Hn 1024
#define NHn 16
#define HDn 64
#define In 4096
#define En 8
#define KTXT 80
#define KIMG 90
#define BKT (Bn*KTXT)   // 320 rows per expert (text)
#define BKI (Bn*KIMG)   // 360 rows per expert (image)

// weight offsets inside the big split-weight buffers (elements)
static const long long W_SAIN  = 0;
static const long long W_SAOUT = 3145728;
static const long long W_CAIN  = 4194304;
static const long long W_CAOUT = 7340032;
static const long long W_EW1   = 8388608;
static const long long W_EW2   = 41943040;
#define W_TOTAL 75497472

// ---------------- device scratch ----------------
__device__ __nv_bfloat16 g_w_hi[W_TOTAL];
__device__ __nv_bfloat16 g_w_lo[W_TOTAL];
__device__ __nv_bfloat16 g_img_hi[Bn*Vn*Hn];
__device__ __nv_bfloat16 g_img_lo[Bn*Vn*Hn];
__device__ __nv_bfloat16 g_ln_hi[Bn*Tn*Hn];
__device__ __nv_bfloat16 g_ln_lo[Bn*Tn*Hn];
__device__ __nv_bfloat16 g_qkv_hi[Bn*Tn*3*Hn];
__device__ __nv_bfloat16 g_qkv_lo[Bn*Tn*3*Hn];
__device__ __nv_bfloat16 g_attn_hi[Bn*Tn*Hn];
__device__ __nv_bfloat16 g_attn_lo[Bn*Tn*Hn];
__device__ __nv_bfloat16 g_qc_hi[Bn*Tn*Hn];
__device__ __nv_bfloat16 g_qc_lo[Bn*Tn*Hn];
__device__ __nv_bfloat16 g_kv_hi[Bn*Vn*2*Hn];
__device__ __nv_bfloat16 g_kv_lo[Bn*Vn*2*Hn];
__device__ __nv_bfloat16 g_p_hi[Bn*NHn*Tn*Vn];
__device__ __nv_bfloat16 g_p_lo[Bn*NHn*Tn*Vn];
__device__ __nv_bfloat16 g_h_hi[En*BKI*In];
__device__ __nv_bfloat16 g_h_lo[En*BKI*In];

__device__ float g_scores[Bn*NHn*Tn*Vn];
__device__ float g_q1   [Bn*Tn*Hn];
__device__ float g_q2   [Bn*Tn*Hn];
__device__ float g_probs_txt[Bn*Tn*En];
__device__ float g_probs_img[Bn*Vn*En];
__device__ float g_ctx_img[Bn*Hn];
__device__ float g_ctx_txt[Bn*Hn];
__device__ float g_cp_img[Bn*En];
__device__ float g_cp_txt[Bn*En];
__device__ int   g_sel_txt[En*BKT];
__device__ int   g_sel_img[En*BKI];
__device__ int   g_pos_txt[Bn*En*Tn];
__device__ int   g_pos_img[Bn*En*Vn];
__device__ float g_down [En*BKI*Hn];

// ---------------- helpers ----------------
__device__ __forceinline__ uint32_t smem_u32(const void* p){
    uint32_t a;
    asm("{ .reg .u64 t; cvta.to.shared.u64 t, %1; cvt.u32.u64 %0, t; }" : "=r"(a) : "l"(p));
    return a;
}
__device__ __forceinline__ float gelu_tanh(float x){
    float x3 = x*x*x;
    return 0.5f*x*(1.0f+tanhf(0.7978845608028654f*(x+0.044715f*x3)));
}
__device__ __forceinline__ void ldm_x4(uint32_t& r0,uint32_t& r1,uint32_t& r2,uint32_t& r3, uint32_t addr){
    asm volatile("ldmatrix.sync.aligned.m8n8.x4.shared.b16 {%0,%1,%2,%3}, [%4];"
      : "=r"(r0),"=r"(r1),"=r"(r2),"=r"(r3) : "r"(addr));
}
__device__ __forceinline__ void ldm_x2(uint32_t& r0,uint32_t& r1, uint32_t addr){
    asm volatile("ldmatrix.sync.aligned.m8n8.x2.shared.b16 {%0,%1}, [%2];"
      : "=r"(r0),"=r"(r1) : "r"(addr));
}
__device__ __forceinline__ void mma_bf16(float* c, const uint32_t* a, const uint32_t* b){
    asm volatile("mma.sync.aligned.m16n8k16.row.col.f32.bf16.bf16.f32 "
      "{%0,%1,%2,%3}, {%4,%5,%6,%7}, {%8,%9}, {%0,%1,%2,%3};"
      : "+f"(c[0]),"+f"(c[1]),"+f"(c[2]),"+f"(c[3])
      : "r"(a[0]),"r"(a[1]),"r"(a[2]),"r"(a[3]), "r"(b[0]),"r"(b[1]));
}
__device__ __forceinline__ void cp16(uint32_t d, const void* s, bool ok){
    asm volatile("cp.async.cg.shared.global [%0], [%1], 16, %2;"
      :: "r"(d), "l"(s), "r"(ok ? 16 : 0) : "memory");
}
#define CP_COMMIT() asm volatile("cp.async.commit_group;" ::: "memory")
#define CP_WAIT1() asm volatile("cp.async.wait_group 1;" ::: "memory")
#define CP_WAIT0() asm volatile("cp.async.wait_group 0;" ::: "memory")

__device__ __forceinline__ void split2(float x, float y, uint32_t& hv, uint32_t& lv){
    __nv_bfloat162 h = __floats2bfloat162_rn(x, y);
    __nv_bfloat162 l = __floats2bfloat162_rn(x - __bfloat162float(h.x), y - __bfloat162float(h.y));
    hv = *(uint32_t*)&h; lv = *(uint32_t*)&l;
}

#define LDS 40           // smem row stride in bf16

// =========================================================================
// WIDE HMMA bf16x3 GEMM: CTA tile 128x256, warp tile 64x64 (2x4 warps).
// TRB only. cp.async double-buffered. Full per-(b,h) offset plumbing.
// =========================================================================
#define W_ABUF (128*LDS*2)
#define W_BBUF (256*LDS*2)
#define W_STG  (2*W_ABUF + 2*W_BBUF)
#define SMW    (2*W_STG)

template<bool BIAS, bool RES, bool GELU, bool GATHER, bool OUTF32, bool OUTSPLIT>
__global__ void __launch_bounds__(256, 1)
mma_gemm_wide(const __nv_bfloat16* __restrict__ Ahi, const __nv_bfloat16* __restrict__ Alo,
              const __nv_bfloat16* __restrict__ Bhi, const __nv_bfloat16* __restrict__ Blo,
              const float* __restrict__ bias, const float* __restrict__ res,
              float* __restrict__ C, __nv_bfloat16* __restrict__ Chi, __nv_bfloat16* __restrict__ Clo,
              int M, int N, int K, int lda, int ldb, int ldc,
              long long aOffB, long long aOffH, long long bOffB, long long bOffH,
              long long cOffB, long long cOffH, long long biasOffH,
              int nh, const int* __restrict__ gidx, int gStride)
{
    extern __shared__ char dynsmem[];
    uint32_t sbase = smem_u32(dynsmem);

    int tid = threadIdx.x;
    int wid = tid >> 5, lane = tid & 31;
    int wm = wid & 1, wn = wid >> 1;        // 2 x 4 warps, warp tile 64x64
    int z = blockIdx.z;
    int b = z / nh, h = z - b*nh;
    const __nv_bfloat16* AhB = GATHER ? Ahi : (Ahi + (long long)b*aOffB + (long long)h*aOffH);
    const __nv_bfloat16* AlB = GATHER ? Alo : (Alo + (long long)b*aOffB + (long long)h*aOffH);
    const __nv_bfloat16* BhB = Bhi + (long long)b*bOffB + (long long)h*bOffH;
    const __nv_bfloat16* BlB = Blo + (long long)b*bOffB + (long long)h*bOffH;
    const float* biasb = BIAS ? (bias + (long long)h*biasOffH) : nullptr;
    const float* resb  = RES  ? (res  + (long long)b*cOffB + (long long)h*cOffH) : nullptr;
    int row0 = blockIdx.y * 128, col0 = blockIdx.x * 256;
    int NC = K >> 5;

    float acc[4][8][4] = {};

    auto load_chunk = [&](int c, int s){
        int k0 = c << 5;
        uint32_t st = sbase + s*W_STG;
        #pragma unroll
        for (int i = 0; i < 2; i++) {
            int seg = tid + i*256;
            int r = seg >> 2, ks = (seg & 3) << 3;
            int grow = row0 + r;
            bool ok = grow < M;
            long long arow;
            if (GATHER) arow = ok ? (long long)gidx[(long long)z*gStride + grow] : 0;
            else        arow = ok ? grow : 0;
            uint32_t doff = (uint32_t)(r*LDS + ks)*2u;
            cp16(st + doff,          AhB + arow*lda + k0 + ks, ok);
            cp16(st + W_ABUF + doff, AlB + arow*lda + k0 + ks, ok);
        }
        #pragma unroll
        for (int i = 0; i < 4; i++) {
            int seg = tid + i*256;
            int r = seg >> 2, ks = (seg & 3) << 3;
            int gcol = col0 + r;
            bool ok = gcol < N;
            long long brow = ok ? gcol : 0;
            uint32_t doff = (uint32_t)(r*LDS + ks)*2u;
            cp16(st + 2*W_ABUF + doff,          BhB + brow*ldb + k0 + ks, ok);
            cp16(st + 2*W_ABUF + W_BBUF + doff, BlB + brow*ldb + k0 + ks, ok);
        }
    };
    load_chunk(0, 0); CP_COMMIT();
    for (int c = 0; c < NC; c++) {
        int s = c & 1;
        if (c + 1 < NC) { load_chunk(c+1, 1-s); CP_COMMIT(); CP_WAIT1(); }
        else            { CP_WAIT0(); }
        __syncthreads();
        uint32_t st = sbase + s*W_STG;
        uint32_t aHiS = st, aLoS = st + W_ABUF;
        uint32_t bHiS = st + 2*W_ABUF, bLoS = st + 2*W_ABUF + W_BBUF;
        #pragma unroll
        for (int kh = 0; kh < 2; kh++) {
            uint32_t bh[8][2], bl[8][2];
            #pragma unroll
            for (int ni = 0; ni < 8; ni++) {
                uint32_t off = ((uint32_t)((wn*64 + ni*8 + (lane & 7))*LDS + kh*16 + ((lane >> 3) & 1)*8)) * 2u;
                ldm_x2(bh[ni][0], bh[ni][1], bHiS + off);
                ldm_x2(bl[ni][0], bl[ni][1], bLoS + off);
            }
            #pragma unroll
            for (int mi = 0; mi < 4; mi++) {
                uint32_t off = ((uint32_t)((wm*64 + mi*16 + (lane & 15))*LDS + kh*16 + (lane >> 4)*8)) * 2u;
                uint32_t ah[4], al[4];
                ldm_x4(ah[0], ah[1], ah[2], ah[3], aHiS + off);
                ldm_x4(al[0], al[1], al[2], al[3], aLoS + off);
                #pragma unroll
                for (int ni = 0; ni < 8; ni++) {
                    mma_bf16(acc[mi][ni], ah, bh[ni]);
                    mma_bf16(acc[mi][ni], ah, bl[ni]);
                    mma_bf16(acc[mi][ni], al, bh[ni]);
                }
            }
        }
        __syncthreads();
    }

    // ---- epilogue ----
    float* Cb = OUTF32 ? (C + (long long)b*cOffB + (long long)h*cOffH) : nullptr;
    __nv_bfloat16* ChB = OUTSPLIT ? (Chi + (long long)b*cOffB + (long long)h*cOffH) : nullptr;
    __nv_bfloat16* ClB = OUTSPLIT ? (Clo + (long long)b*cOffB + (long long)h*cOffH) : nullptr;
    #pragma unroll
    for (int mi = 0; mi < 4; mi++) {
        #pragma unroll
        for (int ni = 0; ni < 8; ni++) {
            int rg = row0 + wm*64 + mi*16 + (lane >> 2);
            int cg = col0 + wn*64 + ni*8 + (lane & 3)*2;
            if (cg >= N) continue;
            #pragma unroll
            for (int half = 0; half < 2; half++) {
                int row = rg + half*8;
                if (row < M) {
                    float v0 = acc[mi][ni][half*2+0];
                    float v1 = acc[mi][ni][half*2+1];
                    if (BIAS) { v0 += biasb[cg]; v1 += biasb[cg+1]; }
                    if (GELU) { v0 = gelu_tanh(v0); v1 = gelu_tanh(v1); }
                    if (RES)  { v0 += resb[(long long)row*ldc + cg]; v1 += resb[(long long)row*ldc + cg + 1]; }
                    if (OUTF32) *(float2*)&Cb[(long long)row*ldc + cg] = make_float2(v0, v1);
                    if (OUTSPLIT) {
                        uint32_t hv, lv;
                        split2(v0, v1, hv, lv);
                        *(uint32_t*)&ChB[(long long)row*ldc + cg] = hv;
                        *(uint32_t*)&ClB[(long long)row*ldc + cg] = lv;
                    }
                }
            }
        }
    }
}

// =========================================================================
// Original HMMA bf16x3 GEMM (attention score / AV shapes).
// WARPM=2: 128x128 tile. WARPM=4: 256x64 tile (NTB AV).
// =========================================================================
template<int WARPM, bool TRB, bool OUTF32, bool OUTSPLIT>
__global__ void __launch_bounds__(256, 2)
mma_gemm(const __nv_bfloat16* __restrict__ Ahi, const __nv_bfloat16* __restrict__ Alo,
         const __nv_bfloat16* __restrict__ Bhi, const __nv_bfloat16* __restrict__ Blo,
         float* __restrict__ C, __nv_bfloat16* __restrict__ Chi, __nv_bfloat16* __restrict__ Clo,
         int M, int N, int K, int lda, int ldb, int ldc,
         long long aOffB, long long aOffH, long long bOffB, long long bOffH,
         long long cOffB, long long cOffH,
         int nh, float alpha)
{
    constexpr int TM = WARPM*64;
    constexpr int TN = (8/WARPM)*32;
    constexpr int ABUF = TM*LDS*2;
    constexpr int BBUF = TN*LDS*2;
    constexpr int STG = 2*ABUF + 2*BBUF;

    extern __shared__ char dynsmem[];
    uint32_t sbase = smem_u32(dynsmem);

    int tid = threadIdx.x;
    int wid = tid >> 5, lane = tid & 31;
    int wm = wid % WARPM, wn = wid / WARPM;
    int z = blockIdx.z;
    int b = z / nh, h = z - b*nh;
    const __nv_bfloat16* AhB = Ahi + (long long)b*aOffB + (long long)h*aOffH;
    const __nv_bfloat16* AlB = Alo + (long long)b*aOffB + (long long)h*aOffH;
    const __nv_bfloat16* BhB = Bhi + (long long)b*bOffB + (long long)h*bOffH;
    const __nv_bfloat16* BlB = Blo + (long long)b*bOffB + (long long)h*bOffH;
    int row0 = blockIdx.y * TM, col0 = blockIdx.x * TN;
    int NC = K >> 5;

    float acc[4][4][4] = {};

    if (TRB) {
        auto load_chunk = [&](int c, int s){
            int k0 = c << 5;
            uint32_t st = sbase + s*STG;
            #pragma unroll
            for (int i = 0; i < TM/64; i++) {
                int seg = tid + i*256;
                int r = seg >> 2, ks = (seg & 3) << 3;
                int grow = row0 + r;
                bool ok = grow < M;
                long long arow = ok ? grow : 0;
                uint32_t doff = (uint32_t)(r*LDS + ks)*2u;
                cp16(st + doff,        AhB + arow*lda + k0 + ks, ok);
                cp16(st + ABUF + doff, AlB + arow*lda + k0 + ks, ok);
            }
            #pragma unroll
            for (int i = 0; i < TN/64; i++) {
                int seg = tid + i*256;
                int r = seg >> 2, ks = (seg & 3) << 3;
                int gcol = col0 + r;
                bool ok = gcol < N;
                long long brow = ok ? gcol : 0;
                uint32_t doff = (uint32_t)(r*LDS + ks)*2u;
                cp16(st + 2*ABUF + doff,        BhB + brow*ldb + k0 + ks, ok);
                cp16(st + 2*ABUF + BBUF + doff, BlB + brow*ldb + k0 + ks, ok);
            }
        };
        load_chunk(0, 0); CP_COMMIT();
        for (int c = 0; c < NC; c++) {
            int s = c & 1;
            if (c + 1 < NC) { load_chunk(c+1, 1-s); CP_COMMIT(); CP_WAIT1(); }
            else            { CP_WAIT0(); }
            __syncthreads();
            uint32_t st = sbase + s*STG;
            uint32_t aHiS = st, aLoS = st + ABUF;
            uint32_t bHiS = st + 2*ABUF, bLoS = st + 2*ABUF + BBUF;
            #pragma unroll
            for (int kh = 0; kh < 2; kh++) {
                uint32_t bh[4][2], bl[4][2];
                #pragma unroll
                for (int ni = 0; ni < 4; ni++) {
                    uint32_t off = ((uint32_t)((wn*32 + ni*8 + (lane & 7))*LDS + kh*16 + ((lane >> 3) & 1)*8)) * 2u;
                    ldm_x2(bh[ni][0], bh[ni][1], bHiS + off);
                    ldm_x2(bl[ni][0], bl[ni][1], bLoS + off);
                }
                #pragma unroll
                for (int mi = 0; mi < 4; mi++) {
                    uint32_t off = ((uint32_t)((wm*64 + mi*16 + (lane & 15))*LDS + kh*16 + (lane >> 4)*8)) * 2u;
                    uint32_t ah[4], al[4];
                    ldm_x4(ah[0], ah[1], ah[2], ah[3], aHiS + off);
                    ldm_x4(al[0], al[1], al[2], al[3], aLoS + off);
                    #pragma unroll
                    for (int ni = 0; ni < 4; ni++) {
                        mma_bf16(acc[mi][ni], ah, bh[ni]);
                        mma_bf16(acc[mi][ni], ah, bl[ni]);
                        mma_bf16(acc[mi][ni], al, bh[ni]);
                    }
                }
            }
            __syncthreads();
        }
    } else {
        uint32_t aHiS = sbase, aLoS = sbase + ABUF;
        uint32_t bHiS = sbase + 2*ABUF, bLoS = sbase + 2*ABUF + BBUF;
        __nv_bfloat16* sBh = (__nv_bfloat16*)(dynsmem + 2*ABUF);
        __nv_bfloat16* sBl = (__nv_bfloat16*)(dynsmem + 2*ABUF + BBUF);
        for (int c = 0; c < NC; c++) {
            int k0 = c << 5;
            #pragma unroll
            for (int i = 0; i < TM/64; i++) {
                int seg = tid + i*256;
                int r = seg >> 2, ks = (seg & 3) << 3;
                int grow = row0 + r;
                uint4 hv = make_uint4(0,0,0,0), lv = make_uint4(0,0,0,0);
                if (grow < M) {
                    hv = *(const uint4*)(AhB + (long long)grow*lda + k0 + ks);
                    lv = *(const uint4*)(AlB + (long long)grow*lda + k0 + ks);
                }
                *(uint4*)(dynsmem + (r*LDS + ks)*2) = hv;
                *(uint4*)(dynsmem + ABUF + (r*LDS + ks)*2) = lv;
            }
            #pragma unroll
            for (int i = 0; i < TN/64; i++) {
                int idx = tid + i*256;
                int kk = idx / (TN/8);
                int n0 = (idx % (TN/8)) * 8;
                int gc = col0 + n0;
                __nv_bfloat16 hv8[8], lv8[8];
                if (gc < N) {
                    *(uint4*)hv8 = *(const uint4*)(BhB + (long long)(k0 + kk)*ldb + gc);
                    *(uint4*)lv8 = *(const uint4*)(BlB + (long long)(k0 + kk)*ldb + gc);
                } else {
                    #pragma unroll
                    for (int j = 0; j < 8; j++){ hv8[j] = __float2bfloat16(0.f); lv8[j] = __float2bfloat16(0.f); }
                }
                #pragma unroll
                for (int j = 0; j < 8; j++) {
                    sBh[(n0 + j)*LDS + kk] = hv8[j];
                    sBl[(n0 + j)*LDS + kk] = lv8[j];
                }
            }
            __syncthreads();
            #pragma unroll
            for (int kh = 0; kh < 2; kh++) {
                uint32_t bh[4][2], bl[4][2];
                #pragma unroll
                for (int ni = 0; ni < 4; ni++) {
                    uint32_t off = ((uint32_t)((wn*32 + ni*8 + (lane & 7))*LDS + kh*16 + ((lane >> 3) & 1)*8)) * 2u;
                    ldm_x2(bh[ni][0], bh[ni][1], bHiS + off);
                    ldm_x2(bl[ni][0], bl[ni][1], bLoS + off);
                }
                #pragma unroll
                for (int mi = 0; mi < 4; mi++) {
                    uint32_t off = ((uint32_t)((wm*64 + mi*16 + (lane & 15))*LDS + kh*16 + (lane >> 4)*8)) * 2u;
                    uint32_t ah[4], al[4];
                    ldm_x4(ah[0], ah[1], ah[2], ah[3], aHiS + off);
                    ldm_x4(al[0], al[1], al[2], al[3], aLoS + off);
                    #pragma unroll
                    for (int ni = 0; ni < 4; ni++) {
                        mma_bf16(acc[mi][ni], ah, bh[ni]);
                        mma_bf16(acc[mi][ni], ah, bl[ni]);
                        mma_bf16(acc[mi][ni], al, bh[ni]);
                    }
                }
            }
            __syncthreads();
        }
    }

    // ---- epilogue ----
    float* Cb = OUTF32 ? (C + (long long)b*cOffB + (long long)h*cOffH) : nullptr;
    __nv_bfloat16* ChB = OUTSPLIT ? (Chi + (long long)b*cOffB + (long long)h*cOffH) : nullptr;
    __nv_bfloat16* ClB = OUTSPLIT ? (Clo + (long long)b*cOffB + (long long)h*cOffH) : nullptr;
    #pragma unroll
    for (int mi = 0; mi < 4; mi++) {
        #pragma unroll
        for (int ni = 0; ni < 4; ni++) {
            int rg = row0 + wm*64 + mi*16 + (lane >> 2);
            int cg = col0 + wn*32 + ni*8 + (lane & 3)*2;
            if (cg >= N) continue;
            #pragma unroll
            for (int half = 0; half < 2; half++) {
                int row = rg + half*8;
                if (row < M) {
                    float v0 = acc[mi][ni][half*2+0]*alpha;
                    float v1 = acc[mi][ni][half*2+1]*alpha;
                    if (OUTF32) *(float2*)&Cb[(long long)row*ldc + cg] = make_float2(v0, v1);
                    if (OUTSPLIT) {
                        uint32_t hv, lv;
                        split2(v0, v1, hv, lv);
                        *(uint32_t*)&ChB[(long long)row*ldc + cg] = hv;
                        *(uint32_t*)&ClB[(long long)row*ldc + cg] = lv;
                    }
                }
            }
        }
    }
}

// ---------------- merged fp32 -> bf16 hi/lo splitter (all 7 regions) ----------------
struct SplitDesc { const float* src; __nv_bfloat16* hi; __nv_bfloat16* lo; int n4; };
struct SplitArgs { SplitDesc d[7]; };

__global__ void split_all(SplitArgs a)
{
    int i = blockIdx.x*256 + threadIdx.x;
    #pragma unroll
    for (int s = 0; s < 7; s++) {
        if (i < a.d[s].n4) {
            float4 v = ((const float4*)a.d[s].src)[i];
            uint32_t h0, l0, h1, l1;
            split2(v.x, v.y, h0, l0);
            split2(v.z, v.w, h1, l1);
            ((uint2*)a.d[s].hi)[i] = make_uint2(h0, h1);
            ((uint2*)a.d[s].lo)[i] = make_uint2(l0, l1);
            return;
        }
        i -= a.d[s].n4;
    }
}

// ---------------- LayerNorm -> hi/lo bf16 ----------------
__global__ void ln_split(const float* __restrict__ x, const float* __restrict__ g,
                         const float* __restrict__ bta,
                         __nv_bfloat16* __restrict__ yhi, __nv_bfloat16* __restrict__ ylo)
{
    long long row = blockIdx.x;
    int tid = threadIdx.x;
    const float4* xr = (const float4*)(x + row*Hn);
    float4 xv = xr[tid];
    float s = xv.x+xv.y+xv.z+xv.w;
    float q = xv.x*xv.x+xv.y*xv.y+xv.z*xv.z+xv.w*xv.w;
    for (int o=16;o;o>>=1){ s += __shfl_down_sync(0xffffffffu,s,o); q += __shfl_down_sync(0xffffffffu,q,o); }
    __shared__ float ss[8], qq[8];
    __shared__ float mv[2];
    int lane = tid&31, wd = tid>>5;
    if (lane==0){ ss[wd]=s; qq[wd]=q; }
    __syncthreads();
    if (tid==0){
        float a=0,c=0;
        #pragma unroll
        for(int i=0;i<8;i++){a+=ss[i]; c+=qq[i];}
        float mean = a*(1.f/Hn);
        float var  = c*(1.f/Hn) - mean*mean;
        mv[0]=mean; mv[1]=rsqrtf(var+1e-5f);
    }
    __syncthreads();
    float mean=mv[0], inv=mv[1];
    float4 gv = ((const float4*)g)[tid];
    float4 bv = ((const float4*)bta)[tid];
    float o0=(xv.x-mean)*inv*gv.x+bv.x;
    float o1=(xv.y-mean)*inv*gv.y+bv.y;
    float o2=(xv.z-mean)*inv*gv.z+bv.z;
    float o3=(xv.w-mean)*inv*gv.w+bv.w;
    uint32_t h0,l0,h1,l1;
    split2(o0,o1,h0,l0);
    split2(o2,o3,h1,l1);
    ((uint2*)(yhi + row*Hn))[tid] = make_uint2(h0,h1);
    ((uint2*)(ylo + row*Hn))[tid] = make_uint2(l0,l1);
}

// ---------------- row softmax fp32 -> hi/lo bf16 ----------------
__global__ void softmax_split(const float* __restrict__ p,
                              __nv_bfloat16* __restrict__ phi, __nv_bfloat16* __restrict__ plo,
                              int cols)
{
    long long row = blockIdx.x;
    const float* r = p + row*cols;
    int tid = threadIdx.x;
    float tmp[5];
    float mx = -1e30f;
    int cnt = 0;
    for (int i=tid;i<cols;i+=128){ float v = r[i]; tmp[cnt++] = v; mx = fmaxf(mx, v); }
    for (int o=16;o;o>>=1) mx = fmaxf(mx, __shfl_xor_sync(0xffffffffu,mx,o));
    __shared__ float sm[4], sq[4];
    if ((tid&31)==0) sm[tid>>5]=mx;
    __syncthreads();
    mx = fmaxf(fmaxf(sm[0],sm[1]),fmaxf(sm[2],sm[3]));
    float sum = 0.f;
    for (int j=0;j<cnt;j++){ float e=__expf(tmp[j]-mx); tmp[j]=e; sum+=e; }
    for (int o=16;o;o>>=1) sum += __shfl_xor_sync(0xffffffffu,sum,o);
    if ((tid&31)==0) sq[tid>>5]=sum;
    __syncthreads();
    sum = sq[0]+sq[1]+sq[2]+sq[3];
    float inv = 1.f/sum;
    cnt = 0;
    for (int i=tid;i<cols;i+=128){
        float v = tmp[cnt++]*inv;
        __nv_bfloat16 hv = __float2bfloat16(v);
        __nv_bfloat16 lv = __float2bfloat16(v - __bfloat162float(hv));
        phi[row*cols + i] = hv;
        plo[row*cols + i] = lv;
    }
}

// ---------------- mean over rows ----------------
__global__ void mean_rows(const float* __restrict__ x, float* __restrict__ out, int rows)
{
    int b = blockIdx.x, tid = threadIdx.x;
    const float4* xb = (const float4*)(x + (long long)b*rows*Hn);
    float4 acc = {0,0,0,0};
    for (int v=0; v<rows; v++){
        float4 t = xb[v*(Hn/4) + tid];
        acc.x+=t.x; acc.y+=t.y; acc.z+=t.z; acc.w+=t.w;
    }
    float inv = 1.f/rows;
    float4 o = {acc.x*inv, acc.y*inv, acc.z*inv, acc.w*inv};
    ((float4*)(out + (long long)b*Hn))[tid] = o;
}

// ---------------- ctxpart ----------------
__global__ void ctxpart_kernel(const float* __restrict__ ctx, const float* __restrict__ W,
                               const float* __restrict__ bias, float* __restrict__ out)
{
    int z = blockIdx.x; int b = z >> 3, e = z & 7;
    int tid = threadIdx.x;
    const float4* c4 = (const float4*)(ctx + (long long)b*Hn);
    const float4* w4 = (const float4*)(W + (long long)e*2*Hn + Hn);
    float4 c = c4[tid], w = w4[tid];
    float s = c.x*w.x + c.y*w.y + c.z*w.z + c.w*w.w;
    for (int o=16;o;o>>=1) s += __shfl_down_sync(0xffffffffu,s,o);
    __shared__ float sh[8];
    if ((tid&31)==0) sh[tid>>5]=s;
    __syncthreads();
    if (tid==0){ float t=0; for(int i=0;i<8;i++) t+=sh[i]; out[z] = t + bias[e]; }
}

// ---------------- gating ----------------
__global__ void gate_kernel(const float* __restrict__ x, const float* __restrict__ W,
                            const float* __restrict__ cp, float* __restrict__ probs, int S)
{
    int token = blockIdx.x; int b = token / S;
    int tid = threadIdx.x;
    __shared__ float xs[Hn];
    ((float4*)xs)[tid] = ((const float4*)(x + (long long)token*Hn))[tid];
    __syncthreads();
    int w = tid >> 5, lane = tid & 31;
    const float* We = W + (long long)w*2*Hn;
    float s = 0.f;
    for (int hh = lane; hh < Hn; hh += 32) s += xs[hh]*We[hh];
    for (int o=16;o;o>>=1) s += __shfl_down_sync(0xffffffffu,s,o);
    __shared__ float lg[En];
    if (lane==0) lg[w] = s + cp[b*En + w];
    __syncthreads();
    if (tid==0){
        float mx = lg[0];
        #pragma unroll
        for (int e=1;e<En;e++) mx = fmaxf(mx, lg[e]);
        float ev[En]; float sum = 0.f;
        #pragma unroll
        for (int e=0;e<En;e++){ ev[e]=expf(lg[e]-mx); sum+=ev[e]; }
        float inv = 1.f/sum;
        #pragma unroll
        for (int e=0;e<En;e++) probs[(long long)token*En+e]=ev[e]*inv;
    }
}

// ---------------- top-k (bitonic; value desc, index asc) ----------------
__global__ void topk_kernel(const float* __restrict__ probs, int S, int k,
                            int* __restrict__ sel, int* __restrict__ pos)
{
    int z = blockIdx.x; int b = z / En, e = z - b*En;
    int tid = threadIdx.x;
    __shared__ float sv[1024];
    __shared__ int   si[1024];
    for (int i=tid;i<1024;i+=256){
        sv[i] = (i < S) ? probs[((long long)b*S + i)*En + e] : -1e30f;
        si[i] = i;
    }
    __syncthreads();
    for (int ksz=2; ksz<=1024; ksz<<=1){
        for (int j=ksz>>1; j>0; j>>=1){
            for (int i=tid; i<1024; i+=256){
                int ixj = i ^ j;
                if (ixj > i){
                    float v1=sv[i], v2=sv[ixj];
                    int i1=si[i], i2=si[ixj];
                    bool before = (v1 > v2) || (v1 == v2 && i1 < i2);
                    bool asc = ((i & ksz) == 0);
                    if (asc ? !before : before){
                        sv[i]=v2; sv[ixj]=v1; si[i]=i2; si[ixj]=i1;
                    }
                }
            }
            __syncthreads();
        }
    }
    for (int i=tid;i<S;i+=256) pos[(long long)z*S + i] = 0;
    __syncthreads();
    for (int j=tid;j<k;j+=256){
        int s = si[j];
        sel[(long long)e*(Bn*k) + b*k + j] = b*S + s;
        pos[(long long)z*S + s] = b*k + j + 1;
    }
}

// ---------------- combine: down laid out [En][BK][Hn] ----------------
__global__ void combine_kernel(const float* __restrict__ down, const int* __restrict__ pos,
                               const float* __restrict__ resid, float* __restrict__ out,
                               int S, int BK)
{
    int bs = blockIdx.x; int b = bs / S; int s = bs - b*S;
    int tid = threadIdx.x;
    int p[En]; int cnt = 0;
    #pragma unroll
    for (int e=0;e<En;e++){ p[e] = pos[((long long)(b*En+e))*S + s]; cnt += (p[e]>0); }
    float inv = 1.f / (cnt > 0 ? cnt : 1);
    float4 acc = {0,0,0,0};
    #pragma unroll
    for (int e=0;e<En;e++){
        if (p[e] > 0){
            const float4* dr = (const float4*)(down + ((long long)e*BK + (p[e]-1))*Hn);
            float4 d = dr[tid];
            acc.x+=d.x; acc.y+=d.y; acc.z+=d.z; acc.w+=d.w;
        }
    }
    float4 r = ((const float4*)(resid + (long long)bs*Hn))[tid];
    float4 o = {r.x+acc.x*inv, r.y+acc.y*inv, r.z+acc.z*inv, r.w+acc.w*inv};
    ((float4*)(out + (long long)bs*Hn))[tid] = o;
}

// ---------------- host ----------------
extern "C" void kernel_launch(void* const* d_in, const int* in_sizes, int n_in,
                              void* d_out, int out_size)
{
    const float* query    = (const float*)d_in[0];
    const float* image    = (const float*)d_in[1];
    const float* textctx  = (const float*)d_in[2];
    const float* sa_w_in  = (const float*)d_in[3];
    const float* sa_b_in  = (const float*)d_in[4];
    const float* sa_w_out = (const float*)d_in[5];
    const float* sa_b_out = (const float*)d_in[6];
    const float* ca_w_in  = (const float*)d_in[7];
    const float* ca_b_in  = (const float*)d_in[8];
    const float* ca_w_out = (const float*)d_in[9];
    const float* ca_b_out = (const float*)d_in[10];
    const float* gate_img_w = (const float*)d_in[11];
    const float* gate_img_b = (const float*)d_in[12];
    const float* gate_txt_w = (const float*)d_in[13];
    const float* gate_txt_b = (const float*)d_in[14];
    const float* e_w1 = (const float*)d_in[15];
    const float* e_b1 = (const float*)d_in[16];
    const float* e_w2 = (const float*)d_in[17];
    const float* e_b2 = (const float*)d_in[18];
    const float* lnq_g = (const float*)d_in[19];
    const float* lnq_b = (const float*)d_in[20];
    const float* lnc_g = (const float*)d_in[21];
    const float* lnc_b = (const float*)d_in[22];
    const float* lnf_g = (const float*)d_in[23];
    const float* lnf_b = (const float*)d_in[24];

    __nv_bfloat16 *pWh,*pWl,*pImgH,*pImgL,*pLnH,*pLnL,*pQkvH,*pQkvL,*pAttnH,*pAttnL;
    __nv_bfloat16 *pQcH,*pQcL,*pKvH,*pKvL,*pPh,*pPl,*pHh,*pHl;
    float *pSc,*pQ1,*pQ2,*pPt,*pPi,*pCtxI,*pCtxT,*pCpI,*pCpT,*pDown;
    int *pSelT,*pSelI,*pPosT,*pPosI;
    cudaGetSymbolAddress((void**)&pWh,  g_w_hi);
    cudaGetSymbolAddress((void**)&pWl,  g_w_lo);
    cudaGetSymbolAddress((void**)&pImgH,g_img_hi);
    cudaGetSymbolAddress((void**)&pImgL,g_img_lo);
    cudaGetSymbolAddress((void**)&pLnH, g_ln_hi);
    cudaGetSymbolAddress((void**)&pLnL, g_ln_lo);
    cudaGetSymbolAddress((void**)&pQkvH,g_qkv_hi);
    cudaGetSymbolAddress((void**)&pQkvL,g_qkv_lo);
    cudaGetSymbolAddress((void**)&pAttnH,g_attn_hi);
    cudaGetSymbolAddress((void**)&pAttnL,g_attn_lo);
    cudaGetSymbolAddress((void**)&pQcH, g_qc_hi);
    cudaGetSymbolAddress((void**)&pQcL, g_qc_lo);
    cudaGetSymbolAddress((void**)&pKvH, g_kv_hi);
    cudaGetSymbolAddress((void**)&pKvL, g_kv_lo);
    cudaGetSymbolAddress((void**)&pPh,  g_p_hi);
    cudaGetSymbolAddress((void**)&pPl,  g_p_lo);
    cudaGetSymbolAddress((void**)&pHh,  g_h_hi);
    cudaGetSymbolAddress((void**)&pHl,  g_h_lo);
    cudaGetSymbolAddress((void**)&pSc,  g_scores);
    cudaGetSymbolAddress((void**)&pQ1,  g_q1);
    cudaGetSymbolAddress((void**)&pQ2,  g_q2);
    cudaGetSymbolAddress((void**)&pPt,  g_probs_txt);
    cudaGetSymbolAddress((void**)&pPi,  g_probs_img);
    cudaGetSymbolAddress((void**)&pCtxI,g_ctx_img);
    cudaGetSymbolAddress((void**)&pCtxT,g_ctx_txt);
    cudaGetSymbolAddress((void**)&pCpI, g_cp_img);
    cudaGetSymbolAddress((void**)&pCpT, g_cp_txt);
    cudaGetSymbolAddress((void**)&pDown,g_down);
    cudaGetSymbolAddress((void**)&pSelT,g_sel_txt);
    cudaGetSymbolAddress((void**)&pSelI,g_sel_img);
    cudaGetSymbolAddress((void**)&pPosT,g_pos_txt);
    cudaGetSymbolAddress((void**)&pPosI,g_pos_img);

    const int SM2 = 81920;   // 128x128 TRB double-buffered
    const int SM4 = 51200;   // 256x64 NTB
    cudaFuncSetAttribute(mma_gemm<2,true ,true ,false>, cudaFuncAttributeMaxDynamicSharedMemorySize, SM2);
    cudaFuncSetAttribute(mma_gemm<4,false,false,true >, cudaFuncAttributeMaxDynamicSharedMemorySize, SM4);
    cudaFuncSetAttribute(mma_gemm_wide<true,false,false,false,false,true >, cudaFuncAttributeMaxDynamicSharedMemorySize, SMW);
    cudaFuncSetAttribute(mma_gemm_wide<true,true ,false,false,true ,false>, cudaFuncAttributeMaxDynamicSharedMemorySize, SMW);
    cudaFuncSetAttribute(mma_gemm_wide<true,false,true ,true ,false,true >, cudaFuncAttributeMaxDynamicSharedMemorySize, SMW);
    cudaFuncSetAttribute(mma_gemm_wide<true,false,false,false,true ,false>, cudaFuncAttributeMaxDynamicSharedMemorySize, SMW);

    const int BT = Bn*Tn, BV = Bn*Vn;
    float* outQ = (float*)d_out;
    float* outI = outQ + (long long)BT*Hn;

    // 0) pre-split all weights + image tokens in ONE launch
    SplitArgs sa;
    sa.d[0] = { sa_w_in,  pWh+W_SAIN,  pWl+W_SAIN,  3145728/4 };
    sa.d[1] = { sa_w_out, pWh+W_SAOUT, pWl+W_SAOUT, 1048576/4 };
    sa.d[2] = { ca_w_in,  pWh+W_CAIN,  pWl+W_CAIN,  3145728/4 };
    sa.d[3] = { ca_w_out, pWh+W_CAOUT, pWl+W_CAOUT, 1048576/4 };
    sa.d[4] = { e_w1,     pWh+W_EW1,   pWl+W_EW1,   33554432/4 };
    sa.d[5] = { e_w2,     pWh+W_EW2,   pWl+W_EW2,   33554432/4 };
    sa.d[6] = { image,    pImgH,       pImgL,       (Bn*Vn*Hn)/4 };
    int totN4 = 3145728/4 + 1048576/4 + 3145728/4 + 1048576/4 + 33554432/4 + 33554432/4 + (Bn*Vn*Hn)/4;
    split_all<<<(totN4+255)/256,256>>>(sa);

    // 1) self-attention
    ln_split<<<BT,256>>>(query, lnq_g, lnq_b, pLnH, pLnL);
    mma_gemm_wide<true,false,false,false,false,true><<<dim3(12,16,1),256,SMW>>>(
        pLnH,pLnL, pWh+W_SAIN,pWl+W_SAIN, sa_b_in, nullptr, nullptr, pQkvH,pQkvL,
        BT, 3*Hn, Hn, Hn, Hn, 3*Hn,
        0,0, 0,0, 0,0, 0, 1, nullptr,0);
    mma_gemm<2,true,true,false><<<dim3(4,4,Bn*NHn),256,SM2>>>(
        pQkvH,pQkvL, pQkvH+Hn,pQkvL+Hn, pSc, nullptr,nullptr,
        Tn, Tn, HDn, 3*Hn, 3*Hn, Tn,
        (long long)Tn*3*Hn, HDn, (long long)Tn*3*Hn, HDn,
        (long long)NHn*Tn*Tn, (long long)Tn*Tn, NHn, 0.125f);
    softmax_split<<<Bn*NHn*Tn,128>>>(pSc, pPh, pPl, Tn);
    mma_gemm<4,false,false,true><<<dim3(1,2,Bn*NHn),256,SM4>>>(
        pPh,pPl, pQkvH+2*Hn,pQkvL+2*Hn, nullptr, pAttnH,pAttnL,
        Tn, HDn, Tn, Tn, 3*Hn, Hn,
        (long long)NHn*Tn*Tn, (long long)Tn*Tn, (long long)Tn*3*Hn, HDn,
        (long long)Tn*Hn, HDn, NHn, 1.f);
    mma_gemm_wide<true,true,false,false,true,false><<<dim3(4,16,1),256,SMW>>>(
        pAttnH,pAttnL, pWh+W_SAOUT,pWl+W_SAOUT, sa_b_out, query, pQ1, nullptr,nullptr,
        BT, Hn, Hn, Hn, Hn, Hn,
        0,0, 0,0, 0,0, 0, 1, nullptr,0);

    // 2) cross-attention
    ln_split<<<BT,256>>>(pQ1, lnc_g, lnc_b, pLnH, pLnL);
    mma_gemm_wide<true,false,false,false,false,true><<<dim3(4,16,1),256,SMW>>>(
        pLnH,pLnL, pWh+W_CAIN,pWl+W_CAIN, ca_b_in, nullptr, nullptr, pQcH,pQcL,
        BT, Hn, Hn, Hn, Hn, Hn,
        0,0, 0,0, 0,0, 0, 1, nullptr,0);
    mma_gemm_wide<true,false,false,false,false,true><<<dim3(8,18,1),256,SMW>>>(
        pImgH,pImgL, pWh+W_CAIN+(long long)Hn*Hn,pWl+W_CAIN+(long long)Hn*Hn, ca_b_in+Hn, nullptr, nullptr, pKvH,pKvL,
        BV, 2*Hn, Hn, Hn, Hn, 2*Hn,
        0,0, 0,0, 0,0, 0, 1, nullptr,0);
    mma_gemm<2,true,true,false><<<dim3(5,4,Bn*NHn),256,SM2>>>(
        pQcH,pQcL, pKvH,pKvL, pSc, nullptr,nullptr,
        Tn, Vn, HDn, Hn, 2*Hn, Vn,
        (long long)Tn*Hn, HDn, (long long)Vn*2*Hn, HDn,
        (long long)NHn*Tn*Vn, (long long)Tn*Vn, NHn, 0.125f);
    softmax_split<<<Bn*NHn*Tn,128>>>(pSc, pPh, pPl, Vn);
    mma_gemm<4,false,false,true><<<dim3(1,2,Bn*NHn),256,SM4>>>(
        pPh,pPl, pKvH+Hn,pKvL+Hn, nullptr, pAttnH,pAttnL,
        Tn, HDn, Vn, Vn, 2*Hn, Hn,
        (long long)NHn*Tn*Vn, (long long)Tn*Vn, (long long)Vn*2*Hn, HDn,
        (long long)Tn*Hn, HDn, NHn, 1.f);
    mma_gemm_wide<true,true,false,false,true,false><<<dim3(4,16,1),256,SMW>>>(
        pAttnH,pAttnL, pWh+W_CAOUT,pWl+W_CAOUT, ca_b_out, pQ1, pQ2, nullptr,nullptr,
        BT, Hn, Hn, Hn, Hn, Hn,
        0,0, 0,0, 0,0, 0, 1, nullptr,0);

    // 3) gating
    mean_rows<<<Bn,256>>>(image, pCtxI, Vn);
    mean_rows<<<Bn,256>>>(textctx, pCtxT, Ln);
    ctxpart_kernel<<<Bn*En,256>>>(pCtxT, gate_img_w, gate_img_b, pCpI);
    ctxpart_kernel<<<Bn*En,256>>>(pCtxI, gate_txt_w, gate_txt_b, pCpT);
    gate_kernel<<<BV,256>>>(image, gate_img_w, pCpI, pPi, Vn);
    gate_kernel<<<BT,256>>>(pQ2, gate_txt_w, pCpT, pPt, Tn);
    topk_kernel<<<Bn*En,256>>>(pPt, Tn, KTXT, pSelT, pPosT);
    topk_kernel<<<Bn*En,256>>>(pPi, Vn, KIMG, pSelI, pPosI);

    // 4) text MoE: per-expert batched M = 320, grid z = expert (b=0, h=e)
    ln_split<<<BT,256>>>(pQ2, lnf_g, lnf_b, pLnH, pLnL);
    mma_gemm_wide<true,false,true,true,false,true><<<dim3(16,3,En),256,SMW>>>(
        pLnH,pLnL, pWh+W_EW1,pWl+W_EW1, e_b1, nullptr, nullptr, pHh,pHl,
        BKT, In, Hn, Hn, Hn, In,
        0,0, 0,(long long)In*Hn, 0,(long long)BKT*In, (long long)In,
        En, pSelT, BKT);
    mma_gemm_wide<true,false,false,false,true,false><<<dim3(4,3,En),256,SMW>>>(
        pHh,pHl, pWh+W_EW2,pWl+W_EW2, e_b2, nullptr, pDown, nullptr,nullptr,
        BKT, Hn, In, In, In, Hn,
        0,(long long)BKT*In, 0,(long long)Hn*In, 0,(long long)BKT*Hn, (long long)Hn,
        En, nullptr,0);
    combine_kernel<<<BT,256>>>(pDown, pPosT, pQ2, outQ, Tn, BKT);

    // 5) image MoE: per-expert batched M = 360
    mma_gemm_wide<true,false,true,true,false,true><<<dim3(16,3,En),256,SMW>>>(
        pImgH,pImgL, pWh+W_EW1,pWl+W_EW1, e_b1, nullptr, nullptr, pHh,pHl,
        BKI, In, Hn, Hn, Hn, In,
        0,0, 0,(long long)In*Hn, 0,(long long)BKI*In, (long long)In,
        En, pSelI, BKI);
    mma_gemm_wide<true,false,false,false,true,false><<<dim3(4,3,En),256,SMW>>>(
        pHh,pHl, pWh+W_EW2,pWl+W_EW2, e_b2, nullptr, pDown, nullptr,nullptr,
        BKI, Hn, In, In, In, Hn,
        0,(long long)BKI*In, 0,(long long)Hn*In, 0,(long long)BKI*Hn, (long long)Hn,
        En, nullptr,0);
    combine_kernel<<<BV,256>>>(pDown, pPosI, image, outI, Vn, BKI);
}